// round 16
// baseline (speedup 1.0000x reference)
#include <cuda_runtime.h>

#define B_ 64
#define R_ 32
#define N_ 16384
#define D_ 64
#define O_ 8
#define SPLIT_ 8
#define CHUNK_ (N_ / SPLIT_)    /* 2048 = 256 threads * 8 n */
#define THREADS_ 256
#define NWARP_ (THREADS_ / 32)

// Plain-store partials: every slot written every launch -> no zeroing pass.
__device__ __align__(16) float g_part[B_][SPLIT_][D_];
__device__ float g_cnt[B_][SPLIT_];
// Completion counters (zero-init .bss; finalizer resets them each launch).
__device__ unsigned g_done[B_];

// ---------------------------------------------------------------------------
// Single launch, SINGLE WAVE. grid = (B, 8) = 512 blocks, block = 256;
// thread owns 8 consecutive n -> 4 independent uint4 mask loads in flight
// (2 per array), doubling per-warp MLP vs the SPLIT-16 version.
// Masks are WORD-typed (int32 0/1 or f32 0.0/1.0): nonzero word == true.
// o_types int4 loaded only for 4-n groups with a mask hit (two independent
// conditional loads). Sparse hctx rows gathered WARP-COOPERATIVELY: one
// coalesced 256B load per hit, norm via butterfly reduce, per-lane register
// accumulators. Last block per b finalizes its 32 outputs.
// ---------------------------------------------------------------------------
__global__ __launch_bounds__(THREADS_)
void ssfw_fused(const float* __restrict__ l_local,
                const float* __restrict__ hctx,
                const float* __restrict__ lambda_so,
                const int*   __restrict__ center_o,
                const int*   __restrict__ o_types,
                const unsigned* __restrict__ adj,
                const unsigned* __restrict__ two,
                float*       __restrict__ out) {
    const int b    = blockIdx.x;
    const int part = blockIdx.y;
    const int tid  = threadIdx.x;
    const int warp = tid >> 5;
    const int lane = tid & 31;

    __shared__ __align__(16) float s_part[NWARP_][D_];
    __shared__ int   s_wcnt[NWARP_];
    __shared__ int   s_last;

    const int n_glob = b * N_ + part * CHUNK_ + tid * 8;   // fits in int (max 1M)

    // word masks: 2 independent uint4 per array (32B, coalesced across warp)
    const uint4* wa = (const uint4*)(adj + n_glob);
    const uint4* wt = (const uint4*)(two + n_glob);
    uint4 va0 = wa[0], va1 = wa[1];
    uint4 vt0 = wt[0], vt1 = wt[1];
    const int ctr = center_o[b];

    const unsigned m0 = va0.x | vt0.x, m1 = va0.y | vt0.y;
    const unsigned m2 = va0.z | vt0.z, m3 = va0.w | vt0.w;
    const unsigned m4 = va1.x | vt1.x, m5 = va1.y | vt1.y;
    const unsigned m6 = va1.z | vt1.z, m7 = va1.w | vt1.w;

    // o_types: conditional per 4-n group; the two loads are independent
    int hb = 0;
    if (m0 | m1 | m2 | m3) {
        const int4 ov = *(const int4*)(o_types + n_glob);
        if (m0 && ov.x == ctr) hb |= 1;
        if (m1 && ov.y == ctr) hb |= 2;
        if (m2 && ov.z == ctr) hb |= 4;
        if (m3 && ov.w == ctr) hb |= 8;
    }
    if (m4 | m5 | m6 | m7) {
        const int4 ov = *(const int4*)(o_types + n_glob + 4);
        if (m4 && ov.x == ctr) hb |= 16;
        if (m5 && ov.y == ctr) hb |= 32;
        if (m6 && ov.z == ctr) hb |= 64;
        if (m7 && ov.w == ctr) hb |= 128;
    }

    // ---- warp-cooperative gather: per-lane register accumulator ----
    // lane owns dims {2*lane, 2*lane+1}
    float accx = 0.0f, accy = 0.0f;
    int   wcnt = 0;                 // warp-uniform
    unsigned hitmask = __ballot_sync(0xffffffffu, hb != 0);
    while (hitmask) {
        int src = __ffs(hitmask) - 1;
        hitmask &= hitmask - 1;
        int shb = __shfl_sync(0xffffffffu, hb, src);
        int snb = __shfl_sync(0xffffffffu, n_glob, src);
        #pragma unroll
        for (int j = 0; j < 8; j++) {
            if ((shb >> j) & 1) {
                wcnt++;
                const float2 v = ((const float2*)(hctx + (long long)(snb + j) * D_))[lane];
                float sq = v.x * v.x + v.y * v.y;
                #pragma unroll
                for (int o = 16; o > 0; o >>= 1)
                    sq += __shfl_xor_sync(0xffffffffu, sq, o);
                float rn = rsqrtf(fmaxf(sq, 1e-12f));
                accx += v.x * rn;
                accy += v.y * rn;
            }
        }
    }
    s_part[warp][lane * 2]     = accx;
    s_part[warp][lane * 2 + 1] = accy;
    if (lane == 0) s_wcnt[warp] = wcnt;
    __syncthreads();

    // ---- reduce 8 warp slices, publish partials ----
    if (tid < D_) {
        float acc = 0.0f;
        #pragma unroll
        for (int w = 0; w < NWARP_; w++) acc += s_part[w][tid];
        g_part[b][part][tid] = acc;
    }
    if (tid == 0) {
        int c = 0;
        #pragma unroll
        for (int w = 0; w < NWARP_; w++) c += s_wcnt[w];
        g_cnt[b][part] = (float)c;
    }

    // ---- last-block-done detection (release atomic orders the stores) ----
    if (tid == 0) {
        unsigned old;
        asm volatile("atom.release.gpu.global.add.u32 %0, [%1], 1;"
                     : "=r"(old) : "l"(&g_done[b]) : "memory");
        s_last = (old == SPLIT_ - 1);
    }
    __syncthreads();
    if (!s_last) return;

    // ---- finalize b (this block only) ----
    __shared__ __align__(16) float s_sum[D_];
    __shared__ float s_nv;
    if (tid < D_) {
        float acc = 0.0f;
        #pragma unroll
        for (int p = 0; p < SPLIT_; p++) acc += g_part[b][p][tid];
        s_sum[tid] = acc;
    }
    if (tid == 0) {
        float nv = 0.0f;
        #pragma unroll
        for (int p = 0; p < SPLIT_; p++) nv += g_cnt[b][p];
        s_nv = nv;
        g_done[b] = 0;                  // reset for next graph replay
    }
    __syncthreads();

    const float  nv = s_nv;
    const float2 sv = *(const float2*)(&s_sum[lane * 2]);

    #pragma unroll
    for (int rr = 0; rr < 4; rr++) {    // warp w handles r = w, w+8, w+16, w+24
        const int r = warp + rr * 8;
        const float2* lrow = (const float2*)(l_local + ((long long)b * R_ + r) * D_);
        float2 lv = lrow[lane];

        float sq = lv.x * lv.x + lv.y * lv.y;
        float dp = lv.x * sv.x + lv.y * sv.y;
        #pragma unroll
        for (int o = 16; o > 0; o >>= 1) {
            sq += __shfl_xor_sync(0xffffffffu, sq, o);
            dp += __shfl_xor_sync(0xffffffffu, dp, o);
        }
        if (lane == 0) {
            float rinv = rsqrtf(fmaxf(sq, 1e-12f));
            float avg  = rinv * dp / fmaxf(nv, 1e-9f);
            float lam  = lambda_so[r * O_ + ctr];
            float w    = fmaxf(lam / fmaxf(nv, 1.0f), 0.0f) * (1.0f - avg);
            out[b * R_ + r] = w;
        }
    }
}

// ---------------------------------------------------------------------------
// Launch contract
// Inputs (metadata order): 0 l_local [B,R,D] f32, 1 h_context [B,N,D] f32,
// 2 lambda_so [R,O] f32, 3 center_o [B] i32, 4 o_types [B,N] i32,
// 5 adj_mask [B,N] (word-typed bool), 6 two_hop_mask [B,N] (word-typed bool).
// Output [B,R] f32.
// ---------------------------------------------------------------------------
extern "C" void kernel_launch(void* const* d_in, const int* in_sizes, int n_in,
                              void* d_out, int out_size) {
    const float* l_local   = (const float*)d_in[0];
    const float* h_context = (const float*)d_in[1];
    const float* lambda_so = (const float*)d_in[2];
    const int*   center_o  = (const int*)d_in[3];
    const int*   o_types   = (const int*)d_in[4];
    const unsigned* adj_mask = (const unsigned*)d_in[5];
    const unsigned* two_mask = (const unsigned*)d_in[6];
    float*       out       = (float*)d_out;

    ssfw_fused<<<dim3(B_, SPLIT_), THREADS_>>>(l_local, h_context, lambda_so,
                                               center_o, o_types,
                                               adj_mask, two_mask, out);
}